// round 11
// baseline (speedup 1.0000x reference)
#include <cuda_runtime.h>

#define NB 8
#define NT 2048
#define NE 128
#define NH 16

// Q/K/V scratch + split-K partials (allocation-free: __device__ globals)
__device__ float g_Q[NB * NT * NH];
__device__ float g_K[NB * NT * NH];
__device__ float g_V[NB * NT * NH];
// partial state per (job=(b*32+qt)*8+kc, query): l, a[16]  (fixed softmax ref)
__device__ float g_pl[8 * 32 * 8 * 64];
__device__ float g_pa[8 * 32 * 8 * 64 * 16];

typedef unsigned long long u64;

#define MREF 12.0f   // fixed log2-domain softmax reference (|s| << 12 + 80 safe)

__device__ __forceinline__ float ex2f(float x) {
    float y;
    asm("ex2.approx.ftz.f32 %0, %1;" : "=f"(y) : "f"(x));
    return y;
}
// Blackwell packed fp32x2 (2x fp32 FMA throughput; ptxas never auto-fuses)
__device__ __forceinline__ u64 fma2(u64 a, u64 b, u64 c) {
    u64 d; asm("fma.rn.f32x2 %0, %1, %2, %3;" : "=l"(d) : "l"(a), "l"(b), "l"(c)); return d;
}
__device__ __forceinline__ u64 mul2(u64 a, u64 b) {
    u64 d; asm("mul.rn.f32x2 %0, %1, %2;" : "=l"(d) : "l"(a), "l"(b)); return d;
}
__device__ __forceinline__ u64 add2(u64 a, u64 b) {
    u64 d; asm("add.rn.f32x2 %0, %1, %2;" : "=l"(d) : "l"(a), "l"(b)); return d;
}
__device__ __forceinline__ u64 pack2(float lo, float hi) {
    u64 r; asm("mov.b64 %0, {%1,%2};" : "=l"(r) : "f"(lo), "f"(hi)); return r;
}
__device__ __forceinline__ void unpack2(u64 v, float& lo, float& hi) {
    asm("mov.b64 {%0,%1}, %2;" : "=f"(lo), "=f"(hi) : "l"(v));
}

// ---------------------------------------------------------------------------
// Kernel 1: fused QKV projection, balanced 2D tile + high occupancy.
// 16 tokens/CTA (grid 1024). Thread = (colg = tid&3: 12 cols,
// tokg = (tid>>2)&7: 2 tokens, eq = tid>>5: 32 e-rows, warp-uniform).
// Per e-row: 2 conflict-free scalar x-LDS + 3 quad-broadcast W-LDS.128
// feed 12 fma2. e-quarters merged via smem stage (reusing the W tile).
// smem 35KB -> 5 CTAs/SM; grid supplies ~6.9 CTAs/SM.
// ---------------------------------------------------------------------------
__global__ __launch_bounds__(128, 5) void qkv_kernel(
    const float* __restrict__ x,
    const float* __restrict__ Wq,
    const float* __restrict__ Wk,
    const float* __restrict__ Wv)
{
    __shared__ float sXf[16 * 129];                // 8.3KB
    __shared__ __align__(16) float sWf[128 * 52];  // 26.6KB; reused as stage
    const int tid  = threadIdx.x;
    const int tok0 = blockIdx.x * 16;

    // x tile: 16 tok x 32 f4 = 512 f4, coalesced loads, scalar stores
    const float4* xg = reinterpret_cast<const float4*>(x) + (size_t)tok0 * 32;
#pragma unroll
    for (int i = 0; i < 4; i++) {
        int idx = i * 128 + tid;
        int tok = idx >> 5, e4 = idx & 31;
        float4 v = xg[idx];
        float* p = &sXf[tok * 129 + e4 * 4];
        p[0] = v.x; p[1] = v.y; p[2] = v.z; p[3] = v.w;
    }
    // W: 1536 f4 into padded rows (stride 52 floats, 16B-aligned)
    const float4* wq4 = reinterpret_cast<const float4*>(Wq);
    const float4* wk4 = reinterpret_cast<const float4*>(Wk);
    const float4* wv4 = reinterpret_cast<const float4*>(Wv);
#pragma unroll
    for (int i = 0; i < 12; i++) {
        int idx = i * 128 + tid;
        int e = idx / 12, c4 = idx % 12;
        float4 w = (c4 < 4) ? wq4[e * 4 + c4]
                 : (c4 < 8) ? wk4[e * 4 + (c4 - 4)]
                            : wv4[e * 4 + (c4 - 8)];
        *reinterpret_cast<float4*>(&sWf[e * 52 + c4 * 4]) = w;
    }
    __syncthreads();

    const int colg = tid & 3;            // 12 cols at colg*12
    const int tokg = (tid >> 2) & 7;     // tokens tokg*2, tokg*2+1
    const int eq   = tid >> 5;           // e-quarter (warp-uniform)
    const int lane = tid & 31;
    const float* x0p = &sXf[(tokg * 2)     * 129];
    const float* x1p = &sXf[(tokg * 2 + 1) * 129];

    u64 acc[12];                         // [0..5] token0, [6..11] token1
#pragma unroll
    for (int i = 0; i < 12; i++) acc[i] = 0ull;

    const int e0 = eq * 32;
#pragma unroll 8
    for (int ee = 0; ee < 32; ee++) {
        int e = e0 + ee;
        float xv0 = x0p[e];              // 8-address scalar LDS, conflict-free
        float xv1 = x1p[e];
        const ulonglong2* wp = reinterpret_cast<const ulonglong2*>(
            &sWf[e * 52 + colg * 12]);   // 4-address broadcast LDS.128
        ulonglong2 wa = wp[0], wb = wp[1], wc = wp[2];
        u64 xp0 = pack2(xv0, xv0);
        u64 xp1 = pack2(xv1, xv1);
        acc[0]  = fma2(xp0, wa.x, acc[0]);
        acc[1]  = fma2(xp0, wa.y, acc[1]);
        acc[2]  = fma2(xp0, wb.x, acc[2]);
        acc[3]  = fma2(xp0, wb.y, acc[3]);
        acc[4]  = fma2(xp0, wc.x, acc[4]);
        acc[5]  = fma2(xp0, wc.y, acc[5]);
        acc[6]  = fma2(xp1, wa.x, acc[6]);
        acc[7]  = fma2(xp1, wa.y, acc[7]);
        acc[8]  = fma2(xp1, wb.x, acc[8]);
        acc[9]  = fma2(xp1, wb.y, acc[9]);
        acc[10] = fma2(xp1, wc.x, acc[10]);
        acc[11] = fma2(xp1, wc.y, acc[11]);
    }
    __syncthreads();                     // W reads done -> reuse sWf as stage

    // merge 4 e-quarters: warps 1..3 stage (12 u64, stride 13), warp 0 adds
    u64* stage = reinterpret_cast<u64*>(sWf);
    if (eq > 0) {
        int base = (eq - 1) * 416 + lane * 13;
#pragma unroll
        for (int j = 0; j < 12; j++) stage[base + j] = acc[j];
    }
    __syncthreads();

    if (eq == 0) {
#pragma unroll
        for (int w = 0; w < 3; w++) {
            int base = w * 416 + lane * 13;
#pragma unroll
            for (int j = 0; j < 12; j++)
                acc[j] = add2(acc[j], stage[base + j]);
        }
        float av[24];
#pragma unroll
        for (int j = 0; j < 12; j++) unpack2(acc[j], av[2 * j], av[2 * j + 1]);
#pragma unroll
        for (int t = 0; t < 2; t++) {
            const int tok = tok0 + tokg * 2 + t;
#pragma unroll
            for (int k = 0; k < 12; k++) {
                int c = colg * 12 + k;
                float* base = (c < 16) ? g_Q : (c < 32) ? g_K : g_V;
                base[(size_t)tok * NH + (c & 15)] = av[t * 12 + k];
            }
        }
    }
}

// ---------------------------------------------------------------------------
// Kernel 2: split-K causal flash attention, FIXED-REFERENCE softmax
// (p = 2^(s-MREF)). Job = (b, qt, kc: 256-key chunk) -> 1152 jobs.
// Warp = key phase (pairs {2r,2r+1} mod 8 -> broadcast LDS), lane = query slot.
// ---------------------------------------------------------------------------
__device__ __forceinline__ void scores2(
    const ulonglong2* __restrict__ kp, const u64* __restrict__ q,
    float& s0a, float& s1a, float& s0b, float& s1b)
{
    ulonglong2 a0 = kp[0], a1 = kp[1], a2 = kp[2], a3 = kp[3];
    ulonglong2 b0 = kp[4], b1 = kp[5], b2 = kp[6], b3 = kp[7];
    u64 t; float lo, hi;
    t = fma2(q[0], a0.x, fma2(q[2], a1.x, fma2(q[4], a2.x, mul2(q[6],  a3.x))));
    t = add2(t, fma2(q[1], a0.y, fma2(q[3], a1.y, fma2(q[5], a2.y, mul2(q[7],  a3.y)))));
    unpack2(t, lo, hi); s0a = lo + hi;
    t = fma2(q[8], a0.x, fma2(q[10],a1.x, fma2(q[12],a2.x, mul2(q[14], a3.x))));
    t = add2(t, fma2(q[9], a0.y, fma2(q[11],a1.y, fma2(q[13],a2.y, mul2(q[15], a3.y)))));
    unpack2(t, lo, hi); s1a = lo + hi;
    t = fma2(q[0], b0.x, fma2(q[2], b1.x, fma2(q[4], b2.x, mul2(q[6],  b3.x))));
    t = add2(t, fma2(q[1], b0.y, fma2(q[3], b1.y, fma2(q[5], b2.y, mul2(q[7],  b3.y)))));
    unpack2(t, lo, hi); s0b = lo + hi;
    t = fma2(q[8], b0.x, fma2(q[10],b1.x, fma2(q[12],b2.x, mul2(q[14], b3.x))));
    t = add2(t, fma2(q[9], b0.y, fma2(q[11],b1.y, fma2(q[13],b2.y, mul2(q[15], b3.y)))));
    unpack2(t, lo, hi); s1b = lo + hi;
}

template<bool MASKED>
__device__ __forceinline__ void updF(
    float sa, float sb, bool oka, bool okb,
    float& l, u64* __restrict__ a,
    const ulonglong2& va0, const ulonglong2& va1,
    const ulonglong2& va2, const ulonglong2& va3,
    const ulonglong2& vb0, const ulonglong2& vb1,
    const ulonglong2& vb2, const ulonglong2& vb3)
{
    float pa = ex2f(sa - MREF);
    float pb = ex2f(sb - MREF);
    if (MASKED) {                 // FSEL, no branch
        pa = oka ? pa : 0.f;
        pb = okb ? pb : 0.f;
    }
    l += pa + pb;
    u64 pap = pack2(pa, pa), pbp = pack2(pb, pb);
    a[0] = fma2(pap, va0.x, fma2(pbp, vb0.x, a[0]));
    a[1] = fma2(pap, va0.y, fma2(pbp, vb0.y, a[1]));
    a[2] = fma2(pap, va1.x, fma2(pbp, vb1.x, a[2]));
    a[3] = fma2(pap, va1.y, fma2(pbp, vb1.y, a[3]));
    a[4] = fma2(pap, va2.x, fma2(pbp, vb2.x, a[4]));
    a[5] = fma2(pap, va2.y, fma2(pbp, vb2.y, a[5]));
    a[6] = fma2(pap, va3.x, fma2(pbp, vb3.x, a[6]));
    a[7] = fma2(pap, va3.y, fma2(pbp, vb3.y, a[7]));
}

__global__ __launch_bounds__(128, 4) void attn_kernel()
{
    __shared__ float4 sbuf[1024];    // K[512] | V[512]; reused for combine
    float4* sK4 = sbuf;
    float4* sV4 = sbuf + 512;

    // job decode: groups g=7..0 (qt in [4g,4g+4), g+1 chunks per qt), heavy first
    const int bid = blockIdx.x;           // 0..1151
    const int b   = bid & 7;
    int rem = bid >> 3;                   // 0..143
    int g = 7;
    while (rem >= 4 * (g + 1)) { rem -= 4 * (g + 1); g--; }
    const int qt = 4 * g + rem / (g + 1);
    const int kc = rem % (g + 1);

    const int tid  = threadIdx.x;
    const int r    = tid >> 5;            // warp id = key-pair phase (uniform)
    const int lane = tid & 31;            // query slot
    const int qg0  = qt * 64 + lane;
    const int qg1  = qg0 + 32;
    const int ks0  = kc << 8;             // 256-key chunk base
    const int ttot = (qt >> 1) + 1;       // total 128-key tiles for this qt
    const int ntiles = min(2, ttot - 2 * kc);

    const float SC = 0.25f * 1.44269504088896340736f;  // H^-0.5 * log2(e)
    u64 q[16];
    {
        const float4* qp0 = reinterpret_cast<const float4*>(g_Q + ((size_t)b * NT + qg0) * NH);
        const float4* qp1 = reinterpret_cast<const float4*>(g_Q + ((size_t)b * NT + qg1) * NH);
#pragma unroll
        for (int i = 0; i < 4; i++) {
            float4 t0 = qp0[i], t1 = qp1[i];
            q[2*i]     = pack2(t0.x * SC, t0.y * SC);
            q[2*i+1]   = pack2(t0.z * SC, t0.w * SC);
            q[8+2*i]   = pack2(t1.x * SC, t1.y * SC);
            q[8+2*i+1] = pack2(t1.z * SC, t1.w * SC);
        }
    }

    float l0 = 0.f, l1 = 0.f;
    u64 a[16];
#pragma unroll
    for (int i = 0; i < 16; i++) a[i] = 0ull;

    const float4* Kg = reinterpret_cast<const float4*>(g_K + (size_t)b * NT * NH);
    const float4* Vg = reinterpret_cast<const float4*>(g_V + (size_t)b * NT * NH);
    const ulonglong2* sK2 = reinterpret_cast<const ulonglong2*>(sK4);
    const ulonglong2* sV2 = reinterpret_cast<const ulonglong2*>(sV4);

    for (int kt = 0; kt < ntiles; kt++) {
        const int kb = ks0 + (kt << 7);   // tile key base
#pragma unroll
        for (int i = 0; i < 4; i++) {
            int idx = i * 128 + tid;
            sK4[idx] = Kg[(size_t)kb * 4 + idx];
            sV4[idx] = Vg[(size_t)kb * 4 + idx];
        }
        __syncthreads();

        if (kb + 127 <= qt * 64) {
            // full tile: 16 key-pairs per warp, no masks
#pragma unroll 4
            for (int jj = 0; jj < 16; jj++) {
                int j0 = 8 * jj + 2 * r;          // warp-uniform
                float s0a, s1a, s0b, s1b;
                scores2(sK2 + j0 * 4, q, s0a, s1a, s0b, s1b);
                const ulonglong2* vp = sV2 + j0 * 4;
                ulonglong2 va0 = vp[0], va1 = vp[1], va2 = vp[2], va3 = vp[3];
                ulonglong2 vb0 = vp[4], vb1 = vp[5], vb2 = vp[6], vb3 = vp[7];
                updF<false>(s0a, s0b, true, true, l0, a,
                            va0, va1, va2, va3, vb0, vb1, vb2, vb3);
                updF<false>(s1a, s1b, true, true, l1, a + 8,
                            va0, va1, va2, va3, vb0, vb1, vb2, vb3);
            }
        } else {
            // diagonal tile: per-lane causal masks via FSEL (p zeroed)
            const int jmax = min(127, qt * 64 + 63 - kb);
            for (int j0 = 2 * r; j0 <= jmax; j0 += 8) {
                float s0a, s1a, s0b, s1b;
                scores2(sK2 + j0 * 4, q, s0a, s1a, s0b, s1b);
                const ulonglong2* vp = sV2 + j0 * 4;
                ulonglong2 va0 = vp[0], va1 = vp[1], va2 = vp[2], va3 = vp[3];
                ulonglong2 vb0 = vp[4], vb1 = vp[5], vb2 = vp[6], vb3 = vp[7];
                int kja = kb + j0, kjb = kja + 1;
                updF<true>(s0a, s0b, kja <= qg0, kjb <= qg0, l0, a,
                           va0, va1, va2, va3, vb0, vb1, vb2, vb3);
                updF<true>(s1a, s1b, kja <= qg1, kjb <= qg1, l1, a + 8,
                           va0, va1, va2, va3, vb0, vb1, vb2, vb3);
            }
        }
        __syncthreads();
    }

    // cross-warp combine (fixed reference -> plain sums): warps 1..3 stage,
    // warp 0 adds. stride-5 ulonglong2 layout, conflict-free.
    ulonglong2* cb = reinterpret_cast<ulonglong2*>(sbuf);
    if (r > 0) {
#pragma unroll
        for (int qi = 0; qi < 2; qi++) {
            int base = ((r - 1) * 2 + qi) * 160 + lane * 5;
            const u64* aq = a + qi * 8;
            cb[base + 0] = make_ulonglong2(aq[0], aq[1]);
            cb[base + 1] = make_ulonglong2(aq[2], aq[3]);
            cb[base + 2] = make_ulonglong2(aq[4], aq[5]);
            cb[base + 3] = make_ulonglong2(aq[6], aq[7]);
            cb[base + 4] = make_ulonglong2(pack2(qi == 0 ? l0 : l1, 0.f), 0ull);
        }
    }
    __syncthreads();

    if (r == 0) {
#pragma unroll
        for (int w = 1; w < 4; w++) {
#pragma unroll
            for (int qi = 0; qi < 2; qi++) {
                int base = ((w - 1) * 2 + qi) * 160 + lane * 5;
                float lw, dummy;
                unpack2(cb[base + 4].x, lw, dummy);
                if (qi == 0) l0 += lw; else l1 += lw;
                u64* aq = a + qi * 8;
#pragma unroll
                for (int i = 0; i < 4; i++) {
                    ulonglong2 t = cb[base + i];
                    aq[2*i]   = add2(aq[2*i],   t.x);
                    aq[2*i+1] = add2(aq[2*i+1], t.y);
                }
            }
        }
        // emit split-K partial (shared fixed reference -> just l and a)
        const int jid = ((b * 32 + qt) << 3) + kc;
        g_pl[jid * 64 + lane]      = l0;
        g_pl[jid * 64 + lane + 32] = l1;
        float oc[32];
#pragma unroll
        for (int i = 0; i < 8; i++) {
            unpack2(a[i],     oc[2*i],    oc[2*i+1]);
            unpack2(a[i + 8], oc[16+2*i], oc[16+2*i+1]);
        }
        float4* p0 = reinterpret_cast<float4*>(&g_pa[(size_t)(jid * 64 + lane) * 16]);
        float4* p1 = reinterpret_cast<float4*>(&g_pa[(size_t)(jid * 64 + lane + 32) * 16]);
#pragma unroll
        for (int i = 0; i < 4; i++) {
            p0[i] = make_float4(oc[4*i],    oc[4*i+1],    oc[4*i+2],    oc[4*i+3]);
            p1[i] = make_float4(oc[16+4*i], oc[16+4*i+1], oc[16+4*i+2], oc[16+4*i+3]);
        }
    }
}

// ---------------------------------------------------------------------------
// Kernel 3: sum <=8 split-K partials per query (shared reference) + normalize.
// ---------------------------------------------------------------------------
__global__ __launch_bounds__(64, 8) void combine_kernel(float* __restrict__ out)
{
    const int bq = blockIdx.x;            // 0..255
    const int b  = bq >> 5, qt = bq & 31;
    const int ql = threadIdx.x;           // 0..63
    const int nc = (qt >> 2) + 1;
    const int base = (b * 32 + qt) << 3;

    float L = 0.f;
    float acc[16];
#pragma unroll
    for (int i = 0; i < 16; i++) acc[i] = 0.f;

    for (int c = 0; c < nc; c++) {
        L += g_pl[(base + c) * 64 + ql];
        const float4* pa = reinterpret_cast<const float4*>(
            &g_pa[(size_t)((base + c) * 64 + ql) * 16]);
#pragma unroll
        for (int i = 0; i < 4; i++) {
            float4 v = pa[i];
            acc[4*i+0] += v.x;
            acc[4*i+1] += v.y;
            acc[4*i+2] += v.z;
            acc[4*i+3] += v.w;
        }
    }
    float inv = 1.0f / L;
    float4* op = reinterpret_cast<float4*>(out + ((size_t)b * NT + qt * 64 + ql) * NH);
#pragma unroll
    for (int i = 0; i < 4; i++)
        op[i] = make_float4(acc[4*i] * inv, acc[4*i+1] * inv,
                            acc[4*i+2] * inv, acc[4*i+3] * inv);
}

extern "C" void kernel_launch(void* const* d_in, const int* in_sizes, int n_in,
                              void* d_out, int out_size)
{
    const float* x  = (const float*)d_in[0];
    const float* Wq = (const float*)d_in[1];
    const float* Wk = (const float*)d_in[2];
    const float* Wv = (const float*)d_in[3];
    float* out = (float*)d_out;

    qkv_kernel<<<1024, 128>>>(x, Wq, Wk, Wv);  // 16384 tokens / 16 per CTA
    attn_kernel<<<1152, 128>>>();              // 256-key split-K jobs
    combine_kernel<<<256, 64>>>(out);          // sum + normalize
}

// round 12
// speedup vs baseline: 1.0474x; 1.0474x over previous
#include <cuda_runtime.h>

#define NB 8
#define NT 2048
#define NE 128
#define NH 16

// Q/K/V scratch + split-K partials (allocation-free: __device__ globals)
__device__ float g_Q[NB * NT * NH];
__device__ float g_K[NB * NT * NH];
__device__ float g_V[NB * NT * NH];
// partial state per (job=(b*32+qt)*8+kc, query): l, a[16]  (fixed softmax ref)
__device__ float g_pl[8 * 32 * 8 * 64];
__device__ float g_pa[8 * 32 * 8 * 64 * 16];

typedef unsigned long long u64;

#define MREF 12.0f   // fixed log2-domain softmax reference (|s| << 12 + 80 safe)

__device__ __forceinline__ float ex2f(float x) {
    float y;
    asm("ex2.approx.ftz.f32 %0, %1;" : "=f"(y) : "f"(x));
    return y;
}
// Blackwell packed fp32x2 (2x fp32 FMA throughput; ptxas never auto-fuses)
__device__ __forceinline__ u64 fma2(u64 a, u64 b, u64 c) {
    u64 d; asm("fma.rn.f32x2 %0, %1, %2, %3;" : "=l"(d) : "l"(a), "l"(b), "l"(c)); return d;
}
__device__ __forceinline__ u64 mul2(u64 a, u64 b) {
    u64 d; asm("mul.rn.f32x2 %0, %1, %2;" : "=l"(d) : "l"(a), "l"(b)); return d;
}
__device__ __forceinline__ u64 add2(u64 a, u64 b) {
    u64 d; asm("add.rn.f32x2 %0, %1, %2;" : "=l"(d) : "l"(a), "l"(b)); return d;
}
__device__ __forceinline__ u64 pack2(float lo, float hi) {
    u64 r; asm("mov.b64 %0, {%1,%2};" : "=l"(r) : "f"(lo), "f"(hi)); return r;
}
__device__ __forceinline__ void unpack2(u64 v, float& lo, float& hi) {
    asm("mov.b64 {%0,%1}, %2;" : "=f"(lo), "=f"(hi) : "l"(v));
}

// ---------------------------------------------------------------------------
// Kernel 1: fused QKV projection, column-split for lean loop + occupancy.
// CTA = 64 tokens x 24 cols (half of Wq|Wk|Wv), grid 512 = 256 tok-tiles x 2.
// Warp = (eh = tid>>6: 64 e-rows, colg = (tid>>5)&1: 12 cols) -> W LDS.128 is
// single-address TRUE broadcast. Lane ts = tid&31 owns tokens {ts, ts+32};
// x scalar LDS bank = (ts+e) mod 32: conflict-free.
// Per e-row: 2 x-LDS + 3 W-LDS feed 24 fma2. smem 47.4KB -> 4 CTAs/SM cap,
// grid gives 3.5/SM.
// ---------------------------------------------------------------------------
__global__ __launch_bounds__(128, 4) void qkv_kernel(
    const float* __restrict__ x,
    const float* __restrict__ Wq,
    const float* __restrict__ Wk,
    const float* __restrict__ Wv)
{
    __shared__ float sXf[64 * 129];                // 33KB; tail reused as stage
    __shared__ __align__(16) float sWf[128 * 28];  // 14KB (24 cols + 4 pad)
    const int tid  = threadIdx.x;
    const int bid  = blockIdx.x;
    const int tok0 = (bid >> 1) * 64;
    const int colh = bid & 1;                      // which 24-col half

    // x tile: 64 tok x 32 f4 = 2048 f4, coalesced loads, scalar stores
    const float4* xg = reinterpret_cast<const float4*>(x) + (size_t)tok0 * 32;
#pragma unroll
    for (int i = 0; i < 16; i++) {
        int idx = i * 128 + tid;
        int tok = idx >> 5, e4 = idx & 31;
        float4 v = xg[idx];
        float* p = &sXf[tok * 129 + e4 * 4];
        p[0] = v.x; p[1] = v.y; p[2] = v.z; p[3] = v.w;
    }
    // W half: 128 e-rows x 24 cols = 768 f4 (row stride 28 floats = 112B, 16B-aligned)
    const float4* wq4 = reinterpret_cast<const float4*>(Wq);
    const float4* wk4 = reinterpret_cast<const float4*>(Wk);
    const float4* wv4 = reinterpret_cast<const float4*>(Wv);
#pragma unroll
    for (int i = 0; i < 6; i++) {
        int idx = i * 128 + tid;       // 0..767
        int e = idx / 6, c4 = idx % 6;
        int col = colh * 24 + c4 * 4;
        int m = col >> 4, h4 = (col & 15) >> 2;
        float4 w = (m == 0) ? wq4[e * 4 + h4]
                 : (m == 1) ? wk4[e * 4 + h4]
                            : wv4[e * 4 + h4];
        *reinterpret_cast<float4*>(&sWf[e * 28 + c4 * 4]) = w;
    }
    __syncthreads();

    const int ts   = tid & 31;           // token slot: tokens ts, ts+32
    const int colg = (tid >> 5) & 1;     // 12 cols (warp-uniform)
    const int eh   = tid >> 6;           // e-half (warp-uniform)
    const float* x0p = &sXf[ts * 129];
    const float* x1p = &sXf[(ts + 32) * 129];

    u64 acc[12];                         // [0..5] token ts, [6..11] token ts+32
#pragma unroll
    for (int i = 0; i < 12; i++) acc[i] = 0ull;

    const int e0 = eh * 64;
#pragma unroll 8
    for (int ee = 0; ee < 64; ee++) {
        int e = e0 + ee;
        float xv0 = x0p[e];              // conflict-free scalar LDS
        float xv1 = x1p[e];
        const ulonglong2* wp = reinterpret_cast<const ulonglong2*>(
            &sWf[e * 28 + colg * 12]);   // single-address broadcast LDS.128
        ulonglong2 wa = wp[0], wb = wp[1], wc = wp[2];
        u64 xp0 = pack2(xv0, xv0);
        u64 xp1 = pack2(xv1, xv1);
        acc[0]  = fma2(xp0, wa.x, acc[0]);
        acc[1]  = fma2(xp0, wa.y, acc[1]);
        acc[2]  = fma2(xp0, wb.x, acc[2]);
        acc[3]  = fma2(xp0, wb.y, acc[3]);
        acc[4]  = fma2(xp0, wc.x, acc[4]);
        acc[5]  = fma2(xp0, wc.y, acc[5]);
        acc[6]  = fma2(xp1, wa.x, acc[6]);
        acc[7]  = fma2(xp1, wa.y, acc[7]);
        acc[8]  = fma2(xp1, wb.x, acc[8]);
        acc[9]  = fma2(xp1, wb.y, acc[9]);
        acc[10] = fma2(xp1, wc.x, acc[10]);
        acc[11] = fma2(xp1, wc.y, acc[11]);
    }
    __syncthreads();                     // x reads done -> reuse sXf as stage

    // merge 2 e-halves: eh1 warps stage (12 u64, stride 13), eh0 warps add
    u64* stage = reinterpret_cast<u64*>(sXf);
    if (eh == 1) {
        int base = (tid & 63) * 13;
#pragma unroll
        for (int j = 0; j < 12; j++) stage[base + j] = acc[j];
    }
    __syncthreads();

    if (eh == 0) {
        int base = tid * 13;
#pragma unroll
        for (int j = 0; j < 12; j++)
            acc[j] = add2(acc[j], stage[base + j]);
        float av[24];
#pragma unroll
        for (int j = 0; j < 12; j++) unpack2(acc[j], av[2 * j], av[2 * j + 1]);
#pragma unroll
        for (int t = 0; t < 2; t++) {
            const int tok = tok0 + ts + t * 32;
#pragma unroll
            for (int k = 0; k < 12; k++) {
                int c = colh * 24 + colg * 12 + k;
                float* base_p = (c < 16) ? g_Q : (c < 32) ? g_K : g_V;
                base_p[(size_t)tok * NH + (c & 15)] = av[t * 12 + k];
            }
        }
    }
}

// ---------------------------------------------------------------------------
// Kernel 2: split-K causal flash attention, FIXED-REFERENCE softmax with
// software-pipelined K prefetch (register double-buffer) in the full-tile
// path. Job = (b, qt, kc: 256-key chunk) -> 1152 jobs. Warp = key phase,
// lane = query slot (owns qt*64+lane and +32).
// ---------------------------------------------------------------------------
__device__ __forceinline__ void scores2r(
    const ulonglong2* __restrict__ k, const u64* __restrict__ q,
    float& s0a, float& s1a, float& s0b, float& s1b)
{
    u64 t; float lo, hi;
    t = fma2(q[0], k[0].x, fma2(q[2], k[1].x, fma2(q[4], k[2].x, mul2(q[6],  k[3].x))));
    t = add2(t, fma2(q[1], k[0].y, fma2(q[3], k[1].y, fma2(q[5], k[2].y, mul2(q[7],  k[3].y)))));
    unpack2(t, lo, hi); s0a = lo + hi;
    t = fma2(q[8], k[0].x, fma2(q[10],k[1].x, fma2(q[12],k[2].x, mul2(q[14], k[3].x))));
    t = add2(t, fma2(q[9], k[0].y, fma2(q[11],k[1].y, fma2(q[13],k[2].y, mul2(q[15], k[3].y)))));
    unpack2(t, lo, hi); s1a = lo + hi;
    t = fma2(q[0], k[4].x, fma2(q[2], k[5].x, fma2(q[4], k[6].x, mul2(q[6],  k[7].x))));
    t = add2(t, fma2(q[1], k[4].y, fma2(q[3], k[5].y, fma2(q[5], k[6].y, mul2(q[7],  k[7].y)))));
    unpack2(t, lo, hi); s0b = lo + hi;
    t = fma2(q[8], k[4].x, fma2(q[10],k[5].x, fma2(q[12],k[6].x, mul2(q[14], k[7].x))));
    t = add2(t, fma2(q[9], k[4].y, fma2(q[11],k[5].y, fma2(q[13],k[6].y, mul2(q[15], k[7].y)))));
    unpack2(t, lo, hi); s1b = lo + hi;
}

template<bool MASKED>
__device__ __forceinline__ void updF(
    float sa, float sb, bool oka, bool okb,
    float& l, u64* __restrict__ a,
    const ulonglong2& va0, const ulonglong2& va1,
    const ulonglong2& va2, const ulonglong2& va3,
    const ulonglong2& vb0, const ulonglong2& vb1,
    const ulonglong2& vb2, const ulonglong2& vb3)
{
    float pa = ex2f(sa - MREF);
    float pb = ex2f(sb - MREF);
    if (MASKED) {                 // FSEL, no branch
        pa = oka ? pa : 0.f;
        pb = okb ? pb : 0.f;
    }
    l += pa + pb;
    u64 pap = pack2(pa, pa), pbp = pack2(pb, pb);
    a[0] = fma2(pap, va0.x, fma2(pbp, vb0.x, a[0]));
    a[1] = fma2(pap, va0.y, fma2(pbp, vb0.y, a[1]));
    a[2] = fma2(pap, va1.x, fma2(pbp, vb1.x, a[2]));
    a[3] = fma2(pap, va1.y, fma2(pbp, vb1.y, a[3]));
    a[4] = fma2(pap, va2.x, fma2(pbp, vb2.x, a[4]));
    a[5] = fma2(pap, va2.y, fma2(pbp, vb2.y, a[5]));
    a[6] = fma2(pap, va3.x, fma2(pbp, vb3.x, a[6]));
    a[7] = fma2(pap, va3.y, fma2(pbp, vb3.y, a[7]));
}

__global__ __launch_bounds__(128, 3) void attn_kernel()
{
    __shared__ float4 sbuf[1024];    // K[512] | V[512]; reused for combine
    float4* sK4 = sbuf;
    float4* sV4 = sbuf + 512;

    // job decode: groups g=7..0 (qt in [4g,4g+4), g+1 chunks per qt), heavy first
    const int bid = blockIdx.x;           // 0..1151
    const int b   = bid & 7;
    int rem = bid >> 3;                   // 0..143
    int g = 7;
    while (rem >= 4 * (g + 1)) { rem -= 4 * (g + 1); g--; }
    const int qt = 4 * g + rem / (g + 1);
    const int kc = rem % (g + 1);

    const int tid  = threadIdx.x;
    const int r    = tid >> 5;            // warp id = key-pair phase (uniform)
    const int lane = tid & 31;            // query slot
    const int qg0  = qt * 64 + lane;
    const int qg1  = qg0 + 32;
    const int ks0  = kc << 8;             // 256-key chunk base
    const int ttot = (qt >> 1) + 1;       // total 128-key tiles for this qt
    const int ntiles = min(2, ttot - 2 * kc);

    const float SC = 0.25f * 1.44269504088896340736f;  // H^-0.5 * log2(e)
    u64 q[16];
    {
        const float4* qp0 = reinterpret_cast<const float4*>(g_Q + ((size_t)b * NT + qg0) * NH);
        const float4* qp1 = reinterpret_cast<const float4*>(g_Q + ((size_t)b * NT + qg1) * NH);
#pragma unroll
        for (int i = 0; i < 4; i++) {
            float4 t0 = qp0[i], t1 = qp1[i];
            q[2*i]     = pack2(t0.x * SC, t0.y * SC);
            q[2*i+1]   = pack2(t0.z * SC, t0.w * SC);
            q[8+2*i]   = pack2(t1.x * SC, t1.y * SC);
            q[8+2*i+1] = pack2(t1.z * SC, t1.w * SC);
        }
    }

    float l0 = 0.f, l1 = 0.f;
    u64 a[16];
#pragma unroll
    for (int i = 0; i < 16; i++) a[i] = 0ull;

    const float4* Kg = reinterpret_cast<const float4*>(g_K + (size_t)b * NT * NH);
    const float4* Vg = reinterpret_cast<const float4*>(g_V + (size_t)b * NT * NH);
    const ulonglong2* sK2 = reinterpret_cast<const ulonglong2*>(sK4);
    const ulonglong2* sV2 = reinterpret_cast<const ulonglong2*>(sV4);

    for (int kt = 0; kt < ntiles; kt++) {
        const int kb = ks0 + (kt << 7);   // tile key base
#pragma unroll
        for (int i = 0; i < 4; i++) {
            int idx = i * 128 + tid;
            sK4[idx] = Kg[(size_t)kb * 4 + idx];
            sV4[idx] = Vg[(size_t)kb * 4 + idx];
        }
        __syncthreads();

        if (kb + 127 <= qt * 64) {
            // full tile, software-pipelined: prefetch next K pair into regs
            ulonglong2 ck[8];
#pragma unroll
            for (int i = 0; i < 8; i++) ck[i] = sK2[(2 * r) * 4 + i];
#pragma unroll
            for (int jj = 0; jj < 16; jj++) {
                int j0 = 8 * jj + 2 * r;          // warp-uniform
                float s0a, s1a, s0b, s1b;
                scores2r(ck, q, s0a, s1a, s0b, s1b);
                ulonglong2 nk[8];
                if (jj < 15) {                    // compile-time (full unroll)
#pragma unroll
                    for (int i = 0; i < 8; i++) nk[i] = sK2[(j0 + 8) * 4 + i];
                }
                const ulonglong2* vp = sV2 + j0 * 4;
                ulonglong2 va0 = vp[0], va1 = vp[1], va2 = vp[2], va3 = vp[3];
                ulonglong2 vb0 = vp[4], vb1 = vp[5], vb2 = vp[6], vb3 = vp[7];
                updF<false>(s0a, s0b, true, true, l0, a,
                            va0, va1, va2, va3, vb0, vb1, vb2, vb3);
                updF<false>(s1a, s1b, true, true, l1, a + 8,
                            va0, va1, va2, va3, vb0, vb1, vb2, vb3);
                if (jj < 15) {
#pragma unroll
                    for (int i = 0; i < 8; i++) ck[i] = nk[i];
                }
            }
        } else {
            // diagonal tile: per-lane causal masks via FSEL (p zeroed)
            const int jmax = min(127, qt * 64 + 63 - kb);
            for (int j0 = 2 * r; j0 <= jmax; j0 += 8) {
                ulonglong2 ck[8];
#pragma unroll
                for (int i = 0; i < 8; i++) ck[i] = sK2[j0 * 4 + i];
                float s0a, s1a, s0b, s1b;
                scores2r(ck, q, s0a, s1a, s0b, s1b);
                const ulonglong2* vp = sV2 + j0 * 4;
                ulonglong2 va0 = vp[0], va1 = vp[1], va2 = vp[2], va3 = vp[3];
                ulonglong2 vb0 = vp[4], vb1 = vp[5], vb2 = vp[6], vb3 = vp[7];
                int kja = kb + j0, kjb = kja + 1;
                updF<true>(s0a, s0b, kja <= qg0, kjb <= qg0, l0, a,
                           va0, va1, va2, va3, vb0, vb1, vb2, vb3);
                updF<true>(s1a, s1b, kja <= qg1, kjb <= qg1, l1, a + 8,
                           va0, va1, va2, va3, vb0, vb1, vb2, vb3);
            }
        }
        __syncthreads();
    }

    // cross-warp combine (fixed reference -> plain sums): warps 1..3 stage,
    // warp 0 adds. stride-5 ulonglong2 layout, conflict-free.
    ulonglong2* cb = reinterpret_cast<ulonglong2*>(sbuf);
    if (r > 0) {
#pragma unroll
        for (int qi = 0; qi < 2; qi++) {
            int base = ((r - 1) * 2 + qi) * 160 + lane * 5;
            const u64* aq = a + qi * 8;
            cb[base + 0] = make_ulonglong2(aq[0], aq[1]);
            cb[base + 1] = make_ulonglong2(aq[2], aq[3]);
            cb[base + 2] = make_ulonglong2(aq[4], aq[5]);
            cb[base + 3] = make_ulonglong2(aq[6], aq[7]);
            cb[base + 4] = make_ulonglong2(pack2(qi == 0 ? l0 : l1, 0.f), 0ull);
        }
    }
    __syncthreads();

    if (r == 0) {
#pragma unroll
        for (int w = 1; w < 4; w++) {
#pragma unroll
            for (int qi = 0; qi < 2; qi++) {
                int base = ((w - 1) * 2 + qi) * 160 + lane * 5;
                float lw, dummy;
                unpack2(cb[base + 4].x, lw, dummy);
                if (qi == 0) l0 += lw; else l1 += lw;
                u64* aq = a + qi * 8;
#pragma unroll
                for (int i = 0; i < 4; i++) {
                    ulonglong2 t = cb[base + i];
                    aq[2*i]   = add2(aq[2*i],   t.x);
                    aq[2*i+1] = add2(aq[2*i+1], t.y);
                }
            }
        }
        // emit split-K partial (shared fixed reference -> just l and a)
        const int jid = ((b * 32 + qt) << 3) + kc;
        g_pl[jid * 64 + lane]      = l0;
        g_pl[jid * 64 + lane + 32] = l1;
        float oc[32];
#pragma unroll
        for (int i = 0; i < 8; i++) {
            unpack2(a[i],     oc[2*i],    oc[2*i+1]);
            unpack2(a[i + 8], oc[16+2*i], oc[16+2*i+1]);
        }
        float4* p0 = reinterpret_cast<float4*>(&g_pa[(size_t)(jid * 64 + lane) * 16]);
        float4* p1 = reinterpret_cast<float4*>(&g_pa[(size_t)(jid * 64 + lane + 32) * 16]);
#pragma unroll
        for (int i = 0; i < 4; i++) {
            p0[i] = make_float4(oc[4*i],    oc[4*i+1],    oc[4*i+2],    oc[4*i+3]);
            p1[i] = make_float4(oc[16+4*i], oc[16+4*i+1], oc[16+4*i+2], oc[16+4*i+3]);
        }
    }
}

// ---------------------------------------------------------------------------
// Kernel 3: sum <=8 split-K partials per query (shared reference) + normalize.
// ---------------------------------------------------------------------------
__global__ __launch_bounds__(64, 8) void combine_kernel(float* __restrict__ out)
{
    const int bq = blockIdx.x;            // 0..255
    const int b  = bq >> 5, qt = bq & 31;
    const int ql = threadIdx.x;           // 0..63
    const int nc = (qt >> 2) + 1;
    const int base = (b * 32 + qt) << 3;

    float L = 0.f;
    float acc[16];
#pragma unroll
    for (int i = 0; i < 16; i++) acc[i] = 0.f;

    for (int c = 0; c < nc; c++) {
        L += g_pl[(base + c) * 64 + ql];
        const float4* pa = reinterpret_cast<const float4*>(
            &g_pa[(size_t)((base + c) * 64 + ql) * 16]);
#pragma unroll
        for (int i = 0; i < 4; i++) {
            float4 v = pa[i];
            acc[4*i+0] += v.x;
            acc[4*i+1] += v.y;
            acc[4*i+2] += v.z;
            acc[4*i+3] += v.w;
        }
    }
    float inv = 1.0f / L;
    float4* op = reinterpret_cast<float4*>(out + ((size_t)b * NT + qt * 64 + ql) * NH);
#pragma unroll
    for (int i = 0; i < 4; i++)
        op[i] = make_float4(acc[4*i] * inv, acc[4*i+1] * inv,
                            acc[4*i+2] * inv, acc[4*i+3] * inv);
}

extern "C" void kernel_launch(void* const* d_in, const int* in_sizes, int n_in,
                              void* d_out, int out_size)
{
    const float* x  = (const float*)d_in[0];
    const float* Wq = (const float*)d_in[1];
    const float* Wk = (const float*)d_in[2];
    const float* Wv = (const float*)d_in[3];
    float* out = (float*)d_out;

    qkv_kernel<<<512, 128>>>(x, Wq, Wk, Wv);   // 256 tok-tiles x 2 col-halves
    attn_kernel<<<1152, 128>>>();              // 256-key split-K jobs
    combine_kernel<<<256, 64>>>(out);          // sum + normalize
}